// round 15
// baseline (speedup 1.0000x reference)
#include <cuda_runtime.h>
#include <cuda_bf16.h>
#include <cuda_fp16.h>
#include <math.h>
#include <stdint.h>

#define BB 2
#define NN_ 4096
#define DD 512
#define HH 8
#define DK 64

typedef __nv_bfloat16 bf16;

// ---------------------------------------------------------------------------
// Scratch (device globals — no allocation allowed)
// ---------------------------------------------------------------------------
__device__ float g_vp[BB * NN_ * DD];
__device__ float g_rowsum[BB * HH * NN_];
__device__ __half g_e[(size_t)BB * HH * NN_ * NN_];      // unnormalized exp, fp16

__device__ __half g_xq_h[BB * NN_ * DD]; __device__ __half g_xq_l[BB * NN_ * DD];
__device__ __half g_xk_h[BB * NN_ * DD]; __device__ __half g_xk_l[BB * NN_ * DD];
__device__ __half g_xv_h[BB * NN_ * DD]; __device__ __half g_xv_l[BB * NN_ * DD];
__device__ __half g_wq_h[DD * DD];
__device__ __half g_wk_h[DD * DD];
__device__ __half g_wv_h[DD * DD];
__device__ __half g_wf_h[DD * DD];
__device__ __half g_qp_h[BB * NN_ * DD]; __device__ __half g_qp_l[BB * NN_ * DD];
__device__ __half g_kp_h[BB * NN_ * DD]; __device__ __half g_kp_l[BB * NN_ * DD];
__device__ __half g_vpt_h[BB * HH * DK * NN_];           // [bh, d, token] fp16
__device__ __half g_ft_h[BB * NN_ * DD]; __device__ __half g_ft_l[BB * NN_ * DD];

// ---------------------------------------------------------------------------
// PTX helpers
// ---------------------------------------------------------------------------
__device__ __forceinline__ uint32_t smem_u32(const void* p) {
    uint32_t a;
    asm("{ .reg .u64 t; cvta.to.shared.u64 t, %1; cvt.u32.u64 %0, t; }"
        : "=r"(a) : "l"(p));
    return a;
}

#define CP16(dst, src) \
    asm volatile("cp.async.cg.shared.global [%0], [%1], 16;" :: "r"(dst), "l"(src))
#define CP_COMMIT() asm volatile("cp.async.commit_group;" ::: "memory")
#define CP_WAIT0()  asm volatile("cp.async.wait_group 0;" ::: "memory")
#define CP_WAIT1()  asm volatile("cp.async.wait_group 1;" ::: "memory")

__device__ __forceinline__ void ldsm4(uint32_t& r0, uint32_t& r1, uint32_t& r2, uint32_t& r3,
                                      uint32_t addr) {
    asm volatile("ldmatrix.sync.aligned.m8n8.x4.shared.b16 {%0,%1,%2,%3}, [%4];"
                 : "=r"(r0), "=r"(r1), "=r"(r2), "=r"(r3) : "r"(addr));
}

__device__ __forceinline__ void mma16816h(float* c,
                                          uint32_t a0, uint32_t a1, uint32_t a2, uint32_t a3,
                                          uint32_t b0, uint32_t b1) {
    asm volatile(
        "mma.sync.aligned.m16n8k16.row.col.f32.f16.f16.f32 "
        "{%0,%1,%2,%3}, {%4,%5,%6,%7}, {%8,%9}, {%0,%1,%2,%3};"
        : "+f"(c[0]), "+f"(c[1]), "+f"(c[2]), "+f"(c[3])
        : "r"(a0), "r"(a1), "r"(a2), "r"(a3), "r"(b0), "r"(b1));
}

__device__ __forceinline__ void split1h(float x, __half& h, __half& l) {
    h = __float2half_rn(x);
    l = __float2half_rn(x - __half2float(h));
}

// fp32 -> fp16 hi/lo split (inputs q,k,v), merged 3-way
__global__ void split3h(const float* x0, const float* x1, const float* x2,
                        __half* h0, __half* h1, __half* h2,
                        __half* l0, __half* l1, __half* l2, int n4)
{
    int i = blockIdx.x * blockDim.x + threadIdx.x;
    if (i >= n4) return;
    int w = blockIdx.y;
    const float* x = (w == 0) ? x0 : (w == 1) ? x1 : x2;
    __half* hi = (w == 0) ? h0 : (w == 1) ? h1 : h2;
    __half* lo = (w == 0) ? l0 : (w == 1) ? l1 : l2;
    float4 v = reinterpret_cast<const float4*>(x)[i];
    __half h[4], l[4];
    split1h(v.x, h[0], l[0]); split1h(v.y, h[1], l[1]);
    split1h(v.z, h[2], l[2]); split1h(v.w, h[3], l[3]);
    uint2 ph, pl;
    ph.x = ((uint32_t)*(uint16_t*)&h[1] << 16) | *(uint16_t*)&h[0];
    ph.y = ((uint32_t)*(uint16_t*)&h[3] << 16) | *(uint16_t*)&h[2];
    pl.x = ((uint32_t)*(uint16_t*)&l[1] << 16) | *(uint16_t*)&l[0];
    pl.y = ((uint32_t)*(uint16_t*)&l[3] << 16) | *(uint16_t*)&l[2];
    reinterpret_cast<uint2*>(hi)[i] = ph;
    reinterpret_cast<uint2*>(lo)[i] = pl;
}

// fp32 -> fp16 (hi only) conversion for 4 weight matrices
__global__ void conv4h(const float* x0, const float* x1, const float* x2, const float* x3,
                       __half* h0, __half* h1, __half* h2, __half* h3, int n4)
{
    int i = blockIdx.x * blockDim.x + threadIdx.x;
    if (i >= n4) return;
    int w = blockIdx.y;
    const float* x = (w == 0) ? x0 : (w == 1) ? x1 : (w == 2) ? x2 : x3;
    __half* hi = (w == 0) ? h0 : (w == 1) ? h1 : (w == 2) ? h2 : h3;
    float4 v = reinterpret_cast<const float4*>(x)[i];
    __half2 a = __floats2half2_rn(v.x, v.y);
    __half2 b = __floats2half2_rn(v.z, v.w);
    uint2 p;
    p.x = *reinterpret_cast<uint32_t*>(&a);
    p.y = *reinterpret_cast<uint32_t*>(&b);
    reinterpret_cast<uint2*>(hi)[i] = p;
}

// vp [B, N, D] fp32 -> vpT fp16 [B*H, DK, N]
__global__ void vtrans_f16(const float* __restrict__ vp, __half* __restrict__ vt)
{
    __shared__ float tile[32][33];
    const int j0 = blockIdx.x * 32;
    const int c0 = blockIdx.y * 32;
    const int b  = blockIdx.z;
    const int tx = threadIdx.x, ty = threadIdx.y;
    for (int rr = ty; rr < 32; rr += 8)
        tile[rr][tx] = vp[((long long)(b * NN_ + j0 + rr)) * DD + c0 + tx];
    __syncthreads();
    for (int rr = ty; rr < 32; rr += 8) {
        int c = c0 + rr;
        int h = c >> 6, dl = c & 63;
        long long idx = ((long long)(b * HH + h) * DK + dl) * NN_ + j0 + tx;
        vt[idx] = __float2half_rn(tile[tx][rr]);
    }
}

// ---------------------------------------------------------------------------
// Shared GEMM mainloop: 2-product fp16 (A_hi + A_lo) x B_hi.
// BM=64, BN=128, BK=32, 2-stage, 8 warps warp-tile 32x32.
// ---------------------------------------------------------------------------
#define GM_SMEM 40960
#define GM_STG  20480u

__device__ __forceinline__ void gemm_mainloop(
    const __half* __restrict__ Ahi, const __half* __restrict__ Alo,
    const __half* __restrict__ Bhi,
    int m0, int n0, uint32_t sb, int tid, int wid, int lane,
    float acc[2][4][4])
{
    const int wm = (wid >> 2) * 32;
    const int wn = (wid & 3) * 32;

    auto load_stage = [&](int kt, int s) {
        const int k0 = kt * 32;
        const uint32_t st = sb + (uint32_t)s * GM_STG;
        for (int i = tid; i < 1024; i += 256) {
            if (i < 512) {
                int t = (i >> 8) & 1, r = (i & 255) >> 2, c = i & 3;
                const __half* src = (t ? Alo : Ahi) + (long long)(m0 + r) * DD + k0 + c * 8;
                CP16(st + (uint32_t)t * 5120u + (uint32_t)(r * 80 + c * 16), (const char*)src);
            } else {
                int j = i - 512;
                int r = j >> 2, c = j & 3;
                const __half* src = Bhi + (long long)(n0 + r) * DD + k0 + c * 8;
                CP16(st + 10240u + (uint32_t)(r * 80 + c * 16), (const char*)src);
            }
        }
    };

    load_stage(0, 0); CP_COMMIT();

    for (int kt = 0; kt < 16; kt++) {
        if (kt < 15) { load_stage(kt + 1, (kt + 1) & 1); CP_COMMIT(); CP_WAIT1(); }
        else { CP_WAIT0(); }
        __syncthreads();
        const uint32_t st = sb + (uint32_t)(kt & 1) * GM_STG;
#pragma unroll
        for (int prod = 0; prod < 2; prod++) {
            const uint32_t Ab = st + ((prod == 1) ? 5120u : 0u);
            const uint32_t Bb = st + 10240u;
#pragma unroll
            for (int kc = 0; kc < 2; kc++) {
                const uint32_t colA = (uint32_t)(kc * 32 + ((lane >> 4) & 1) * 16);
                const uint32_t colB = (uint32_t)(kc * 32 + ((lane >> 3) & 1) * 16);
                uint32_t bf[8];
#pragma unroll
                for (int j = 0; j < 2; j++) {
                    int n = wn + j * 16 + ((lane >> 4) & 1) * 8 + (lane & 7);
                    ldsm4(bf[j * 4 + 0], bf[j * 4 + 1], bf[j * 4 + 2], bf[j * 4 + 3],
                          Bb + (uint32_t)(n * 80) + colB);
                }
#pragma unroll
                for (int mi = 0; mi < 2; mi++) {
                    uint32_t a0, a1, a2, a3;
                    int m = wm + mi * 16 + (lane & 15);
                    ldsm4(a0, a1, a2, a3, Ab + (uint32_t)(m * 80) + colA);
#pragma unroll
                    for (int j = 0; j < 2; j++) {
                        mma16816h(acc[mi][2 * j],     a0, a1, a2, a3, bf[j * 4 + 0], bf[j * 4 + 1]);
                        mma16816h(acc[mi][2 * j + 1], a0, a1, a2, a3, bf[j * 4 + 2], bf[j * 4 + 3]);
                    }
                }
            }
        }
        __syncthreads();
    }
}

// ---------------------------------------------------------------------------
// Merged projection GEMM: grid (4, 128, 3). z=0 Q->fp16 hi/lo, z=1 K->fp16
// hi/lo, z=2 V->fp32.
// ---------------------------------------------------------------------------
__global__ void __launch_bounds__(256, 2)
proj_gemm(const __half* __restrict__ xqh, const __half* __restrict__ xql,
          const __half* __restrict__ xkh, const __half* __restrict__ xkl,
          const __half* __restrict__ xvh, const __half* __restrict__ xvl,
          const __half* __restrict__ wqh, const __half* __restrict__ wkh,
          const __half* __restrict__ wvh,
          __half* __restrict__ qph, __half* __restrict__ qpl,
          __half* __restrict__ kph, __half* __restrict__ kpl,
          float* __restrict__ vp)
{
    extern __shared__ char smem[];
    const int tid = threadIdx.x;
    const int wid = tid >> 5;
    const int lane = tid & 31;
    const uint32_t sb = smem_u32(smem);
    const int n0 = blockIdx.x * 128;
    const int m0 = blockIdx.y * 64;
    const int z = blockIdx.z;

    const __half *Ahi, *Alo, *Bhi;
    if (z == 0)      { Ahi = xqh; Alo = xql; Bhi = wqh; }
    else if (z == 1) { Ahi = xkh; Alo = xkl; Bhi = wkh; }
    else             { Ahi = xvh; Alo = xvl; Bhi = wvh; }

    float acc[2][4][4];
#pragma unroll
    for (int i = 0; i < 2; i++)
#pragma unroll
        for (int j = 0; j < 4; j++)
#pragma unroll
            for (int c = 0; c < 4; c++) acc[i][j][c] = 0.0f;

    gemm_mainloop(Ahi, Alo, Bhi, m0, n0, sb, tid, wid, lane, acc);

    const int wm = (wid >> 2) * 32;
    const int wn = (wid & 3) * 32;
#pragma unroll
    for (int mi = 0; mi < 2; mi++) {
#pragma unroll
        for (int ni = 0; ni < 4; ni++) {
            int r  = wm + mi * 16 + (lane >> 2);
            int cc = wn + ni * 8 + (lane & 3) * 2;
#pragma unroll
            for (int half = 0; half < 2; half++) {
                int row = m0 + r + half * 8;
                int col = n0 + cc;
                float v0 = acc[mi][ni][half * 2 + 0];
                float v1 = acc[mi][ni][half * 2 + 1];
                if (z < 2) {
                    __half h0, l0, h1, l1;
                    split1h(v0, h0, l0); split1h(v1, h1, l1);
                    uint32_t ph = ((uint32_t)*(uint16_t*)&h1 << 16) | *(uint16_t*)&h0;
                    uint32_t pl = ((uint32_t)*(uint16_t*)&l1 << 16) | *(uint16_t*)&l0;
                    __half* Ch = z ? kph : qph;
                    __half* Cl = z ? kpl : qpl;
                    *reinterpret_cast<uint32_t*>(Ch + (long long)row * DD + col) = ph;
                    *reinterpret_cast<uint32_t*>(Cl + (long long)row * DD + col) = pl;
                } else {
                    float2 o; o.x = v0; o.y = v1;
                    *reinterpret_cast<float2*>(vp + (long long)row * DD + col) = o;
                }
            }
        }
    }
}

// ---------------------------------------------------------------------------
// fc GEMM + residual
// ---------------------------------------------------------------------------
__global__ void __launch_bounds__(256, 2)
fc_gemm(const __half* __restrict__ Ahi, const __half* __restrict__ Alo,
        const __half* __restrict__ Bhi,
        float* __restrict__ Cf, const float* __restrict__ R)
{
    extern __shared__ char smem[];
    const int tid = threadIdx.x;
    const int wid = tid >> 5;
    const int lane = tid & 31;
    const uint32_t sb = smem_u32(smem);
    const int n0 = blockIdx.x * 128;
    const int m0 = blockIdx.y * 64;

    float acc[2][4][4];
#pragma unroll
    for (int i = 0; i < 2; i++)
#pragma unroll
        for (int j = 0; j < 4; j++)
#pragma unroll
            for (int c = 0; c < 4; c++) acc[i][j][c] = 0.0f;

    gemm_mainloop(Ahi, Alo, Bhi, m0, n0, sb, tid, wid, lane, acc);

    const int wm = (wid >> 2) * 32;
    const int wn = (wid & 3) * 32;
#pragma unroll
    for (int mi = 0; mi < 2; mi++) {
#pragma unroll
        for (int ni = 0; ni < 4; ni++) {
            int r  = wm + mi * 16 + (lane >> 2);
            int cc = wn + ni * 8 + (lane & 3) * 2;
#pragma unroll
            for (int half = 0; half < 2; half++) {
                int row = m0 + r + half * 8;
                int col = n0 + cc;
                float v0 = acc[mi][ni][half * 2 + 0];
                float v1 = acc[mi][ni][half * 2 + 1];
                float2 r2 = *reinterpret_cast<const float2*>(R + (long long)row * DD + col);
                float2 o; o.x = v0 + r2.x; o.y = v1 + r2.y;
                *reinterpret_cast<float2*>(Cf + (long long)row * DD + col) = o;
            }
        }
    }
}

// ---------------------------------------------------------------------------
// Fused attention, single pass: 2-product fp16 scores, E scratch + rowsum
// + feat fp16 hi/lo. smem 72KB -> 2 CTAs/SM.
// ---------------------------------------------------------------------------
#define FU_SMEM 73728
#define FU_KHI 0u
#define FU_KLO 18432u
#define FU_Q0  36864u
#define FU_QST 9216u
#define FU_V0  55296u
#define FU_VST 9216u

__global__ void __launch_bounds__(256, 2)
fused_attn(const __half* __restrict__ Khi, const __half* __restrict__ Klo,
           const __half* __restrict__ Qhi,
           const __half* __restrict__ Vh,
           __half* __restrict__ E, float* __restrict__ rowsum,
           __half* __restrict__ Fhi, __half* __restrict__ Flo)
{
    extern __shared__ char smem[];
    const int tid = threadIdx.x;
    const int wid = tid >> 5;
    const int lane = tid & 31;
    const uint32_t sb = smem_u32(smem);

    const int m0 = blockIdx.x * 128;
    const int bh = blockIdx.y;
    const int b = bh >> 3, h = bh & 7;
    const long long arow = (long long)(b * NN_ + m0);
    const int coff = h * DK;
    const long long vrow = (long long)bh * DK;

    for (int i = tid; i < 2048; i += 256) {
        int t = i >> 10, r = (i & 1023) >> 3, c = i & 7;
        const __half* src = (t ? Klo : Khi) + (arow + r) * DD + coff + c * 8;
        CP16(sb + (uint32_t)t * 18432u + (uint32_t)(r * 144 + c * 16), (const char*)src);
    }

    auto load_Q = [&](int nb, int s) {
        const long long brow = (long long)b * NN_ + (long long)nb * 64;
        const uint32_t st = sb + FU_Q0 + (uint32_t)s * FU_QST;
        for (int i = tid; i < 512; i += 256) {
            int r = i >> 3, c = i & 7;
            const __half* src = Qhi + (brow + r) * DD + coff + c * 8;
            CP16(st + (uint32_t)(r * 144 + c * 16), (const char*)src);
        }
    };
    auto load_V = [&](int nb, int s) {
        const uint32_t st = sb + FU_V0 + (uint32_t)s * FU_VST;
        for (int i = tid; i < 512; i += 256) {
            int r = i >> 3, c = i & 7;
            CP16(st + (uint32_t)(r * 144 + c * 16),
                 (const char*)(Vh + (vrow + r) * NN_ + nb * 64 + c * 8));
        }
    };

    const int gid = lane >> 2, tig = lane & 3;
    const long long ebase = (long long)bh * NN_ * NN_;
    const int mrow = m0 + wid * 16 + gid;

    float rs0 = 0.0f, rs1 = 0.0f;
    float facc[8][4];
#pragma unroll
    for (int i = 0; i < 8; i++)
#pragma unroll
        for (int c = 0; c < 4; c++) facc[i][c] = 0.0f;

    load_Q(0, 0); load_V(0, 0); CP_COMMIT();

    for (int nb = 0; nb < 64; nb++) {
        if (nb < 63) {
            load_Q(nb + 1, (nb + 1) & 1);
            load_V(nb + 1, (nb + 1) & 1);
            CP_COMMIT(); CP_WAIT1();
        } else { CP_WAIT0(); }
        __syncthreads();

        const uint32_t Qst = sb + FU_Q0 + (uint32_t)(nb & 1) * FU_QST;
        const uint32_t Vst = sb + FU_V0 + (uint32_t)(nb & 1) * FU_VST;

        float sacc[8][4];
#pragma unroll
        for (int i = 0; i < 8; i++)
#pragma unroll
            for (int c = 0; c < 4; c++) sacc[i][c] = 0.0f;

#pragma unroll
        for (int prod = 0; prod < 2; prod++) {
            const uint32_t Ab = sb + ((prod == 1) ? FU_KLO : FU_KHI);
#pragma unroll
            for (int kc = 0; kc < 4; kc++) {
                const uint32_t colA = (uint32_t)(kc * 32 + ((lane >> 4) & 1) * 16);
                const uint32_t colB = (uint32_t)(kc * 32 + ((lane >> 3) & 1) * 16);
                uint32_t a0, a1, a2, a3;
                ldsm4(a0, a1, a2, a3,
                      Ab + (uint32_t)((wid * 16 + (lane & 15)) * 144) + colA);
#pragma unroll
                for (int j = 0; j < 4; j++) {
                    int n = j * 16 + ((lane >> 4) & 1) * 8 + (lane & 7);
                    uint32_t q0, q1, q2, q3;
                    ldsm4(q0, q1, q2, q3, Qst + (uint32_t)(n * 144) + colB);
                    mma16816h(sacc[2 * j],     a0, a1, a2, a3, q0, q1);
                    mma16816h(sacc[2 * j + 1], a0, a1, a2, a3, q2, q3);
                }
            }
        }

#pragma unroll
        for (int kch = 0; kch < 4; kch++) {
            uint32_t a0, a1, a2, a3;
#pragma unroll
            for (int jj = 0; jj < 2; jj++) {
                int j = 2 * kch + jj;
                float e0 = __expf(0.125f * sacc[j][0]);
                float e1 = __expf(0.125f * sacc[j][1]);
                float e2 = __expf(0.125f * sacc[j][2]);
                float e3 = __expf(0.125f * sacc[j][3]);
                rs0 += e0 + e1;
                rs1 += e2 + e3;
                __half2 h01 = __floats2half2_rn(e0, e1);
                __half2 h23 = __floats2half2_rn(e2, e3);
                long long colg = (long long)nb * 64 + j * 8 + tig * 2;
                *reinterpret_cast<uint32_t*>(E + ebase + (long long)mrow * NN_ + colg) =
                    *reinterpret_cast<uint32_t*>(&h01);
                *reinterpret_cast<uint32_t*>(E + ebase + (long long)(mrow + 8) * NN_ + colg) =
                    *reinterpret_cast<uint32_t*>(&h23);
                if (jj == 0) { a0 = *reinterpret_cast<uint32_t*>(&h01);
                               a1 = *reinterpret_cast<uint32_t*>(&h23); }
                else         { a2 = *reinterpret_cast<uint32_t*>(&h01);
                               a3 = *reinterpret_cast<uint32_t*>(&h23); }
            }
            const uint32_t colV = (uint32_t)(kch * 32 + ((lane >> 3) & 1) * 16);
#pragma unroll
            for (int vj = 0; vj < 4; vj++) {
                int n = vj * 16 + ((lane >> 4) & 1) * 8 + (lane & 7);
                uint32_t v0, v1, v2, v3;
                ldsm4(v0, v1, v2, v3, Vst + (uint32_t)(n * 144) + colV);
                mma16816h(facc[2 * vj],     a0, a1, a2, a3, v0, v1);
                mma16816h(facc[2 * vj + 1], a0, a1, a2, a3, v2, v3);
            }
        }
        __syncthreads();
    }

    rs0 += __shfl_xor_sync(~0u, rs0, 1);
    rs0 += __shfl_xor_sync(~0u, rs0, 2);
    rs1 += __shfl_xor_sync(~0u, rs1, 1);
    rs1 += __shfl_xor_sync(~0u, rs1, 2);
    const float inv0 = __frcp_rn(rs0);
    const float inv1 = __frcp_rn(rs1);
    if (tig == 0) {
        rowsum[(long long)bh * NN_ + mrow]     = rs0;
        rowsum[(long long)bh * NN_ + mrow + 8] = rs1;
    }

#pragma unroll
    for (int n8 = 0; n8 < 8; n8++) {
        int col = h * DK + n8 * 8 + tig * 2;
#pragma unroll
        for (int half = 0; half < 2; half++) {
            long long row = (long long)(b * NN_ + mrow + half * 8);
            float inv = half ? inv1 : inv0;
            float v0 = facc[n8][half * 2 + 0] * inv;
            float v1 = facc[n8][half * 2 + 1] * inv;
            __half h0, l0, h1, l1;
            split1h(v0, h0, l0); split1h(v1, h1, l1);
            uint32_t ph = ((uint32_t)*(uint16_t*)&h1 << 16) | *(uint16_t*)&h0;
            uint32_t pl = ((uint32_t)*(uint16_t*)&l1 << 16) | *(uint16_t*)&l0;
            *reinterpret_cast<uint32_t*>(Fhi + row * DD + col) = ph;
            *reinterpret_cast<uint32_t*>(Flo + row * DD + col) = pl;
        }
    }
}

// ---------------------------------------------------------------------------
// attn_norm: attn[row, :] = float(E[row, :]) * rcp(rowsum[row])
// ---------------------------------------------------------------------------
__global__ void __launch_bounds__(256)
attn_norm(const __half* __restrict__ E, const float* __restrict__ rowsum,
          float* __restrict__ A)
{
    const long long row = blockIdx.x;
    const float inv = __frcp_rn(rowsum[row]);
    const uint2* pe = reinterpret_cast<const uint2*>(E + row * (long long)NN_);
    float4* pa = reinterpret_cast<float4*>(A + row * (long long)NN_);
    const int t = threadIdx.x;
#pragma unroll
    for (int i = 0; i < 4; i++) {
        uint2 u = pe[t + i * 256];
        __half2 a = *reinterpret_cast<__half2*>(&u.x);
        __half2 bq = *reinterpret_cast<__half2*>(&u.y);
        float2 fa = __half22float2(a);
        float2 fb = __half22float2(bq);
        float4 o;
        o.x = fa.x * inv; o.y = fa.y * inv;
        o.z = fb.x * inv; o.w = fb.y * inv;
        pa[t + i * 256] = o;
    }
}

// ---------------------------------------------------------------------------
// In-place row LayerNorm
// ---------------------------------------------------------------------------
__global__ void layernorm_rows(float* __restrict__ y,
                               const float* __restrict__ gamma,
                               const float* __restrict__ beta)
{
    const long long base = (long long)blockIdx.x * DD;
    const int t = threadIdx.x;
    const int lane = t & 31, warp = t >> 5;
    __shared__ float red[32];

    float x0 = y[base + t];
    float x1 = y[base + t + 256];

    float s = x0 + x1;
#pragma unroll
    for (int o = 16; o > 0; o >>= 1) s += __shfl_xor_sync(~0u, s, o);
    if (lane == 0) red[warp] = s;
    __syncthreads();
    if (warp == 0) {
        float x = (lane < 8) ? red[lane] : 0.0f;
#pragma unroll
        for (int o = 16; o > 0; o >>= 1) x += __shfl_xor_sync(~0u, x, o);
        if (lane == 0) red[0] = x;
    }
    __syncthreads();
    const float mu = red[0] * (1.0f / DD);
    __syncthreads();

    const float d0 = x0 - mu, d1 = x1 - mu;
    float v = d0 * d0 + d1 * d1;
#pragma unroll
    for (int o = 16; o > 0; o >>= 1) v += __shfl_xor_sync(~0u, v, o);
    if (lane == 0) red[warp] = v;
    __syncthreads();
    if (warp == 0) {
        float x = (lane < 8) ? red[lane] : 0.0f;
#pragma unroll
        for (int o = 16; o > 0; o >>= 1) x += __shfl_xor_sync(~0u, x, o);
        if (lane == 0) red[0] = x;
    }
    __syncthreads();
    const float r = rsqrtf(red[0] * (1.0f / DD) + 1e-5f);

    y[base + t]       = d0 * r * gamma[t]       + beta[t];
    y[base + t + 256] = d1 * r * gamma[t + 256] + beta[t + 256];
}

// ---------------------------------------------------------------------------
extern "C" void kernel_launch(void* const* d_in, const int* in_sizes, int n_in,
                              void* d_out, int out_size)
{
    const float* q    = (const float*)d_in[0];
    const float* k    = (const float*)d_in[1];
    const float* v    = (const float*)d_in[2];
    const float* w_q  = (const float*)d_in[3];
    const float* w_k  = (const float*)d_in[4];
    const float* w_v  = (const float*)d_in[5];
    const float* w_fc = (const float*)d_in[6];
    const float* gam  = (const float*)d_in[7];
    const float* bet  = (const float*)d_in[8];

    float* out  = (float*)d_out;                          // [B,N,D]
    float* attn = out + (long long)BB * NN_ * DD;         // [B,H,N,N]

    float *vp, *rsum;
    __half* eptr;
    cudaGetSymbolAddress((void**)&vp,   g_vp);
    cudaGetSymbolAddress((void**)&rsum, g_rowsum);
    cudaGetSymbolAddress((void**)&eptr, g_e);
    __half *xqh, *xql, *xkh, *xkl, *xvh, *xvl;
    __half *wqh, *wkh, *wvh, *wfh;
    __half *qph, *qpl, *kph, *kpl, *vth, *fth, *ftl;
    cudaGetSymbolAddress((void**)&xqh, g_xq_h); cudaGetSymbolAddress((void**)&xql, g_xq_l);
    cudaGetSymbolAddress((void**)&xkh, g_xk_h); cudaGetSymbolAddress((void**)&xkl, g_xk_l);
    cudaGetSymbolAddress((void**)&xvh, g_xv_h); cudaGetSymbolAddress((void**)&xvl, g_xv_l);
    cudaGetSymbolAddress((void**)&wqh, g_wq_h);
    cudaGetSymbolAddress((void**)&wkh, g_wk_h);
    cudaGetSymbolAddress((void**)&wvh, g_wv_h);
    cudaGetSymbolAddress((void**)&wfh, g_wf_h);
    cudaGetSymbolAddress((void**)&qph, g_qp_h); cudaGetSymbolAddress((void**)&qpl, g_qp_l);
    cudaGetSymbolAddress((void**)&kph, g_kp_h); cudaGetSymbolAddress((void**)&kpl, g_kp_l);
    cudaGetSymbolAddress((void**)&vth, g_vpt_h);
    cudaGetSymbolAddress((void**)&fth, g_ft_h); cudaGetSymbolAddress((void**)&ftl, g_ft_l);

    static bool init_done = false;
    static cudaStream_t s_side;
    static cudaEvent_t ev_fused, ev_norm, ev_split;
    if (!init_done) {
        cudaFuncSetAttribute(proj_gemm,  cudaFuncAttributeMaxDynamicSharedMemorySize, GM_SMEM);
        cudaFuncSetAttribute(fc_gemm,    cudaFuncAttributeMaxDynamicSharedMemorySize, GM_SMEM);
        cudaFuncSetAttribute(fused_attn, cudaFuncAttributeMaxDynamicSharedMemorySize, FU_SMEM);
        cudaStreamCreateWithFlags(&s_side, cudaStreamNonBlocking);
        cudaEventCreateWithFlags(&ev_fused, cudaEventDisableTiming);
        cudaEventCreateWithFlags(&ev_norm, cudaEventDisableTiming);
        cudaEventCreateWithFlags(&ev_split, cudaEventDisableTiming);
        init_done = true;
    }

    // The harness calls us on its (capture) stream = legacy default stream 0.
    cudaStream_t s0 = 0;

    const int M = BB * NN_;          // 8192
    const int n4i = M * DD / 4;
    const int n4w = DD * DD / 4;

    // 1) splits/conversions
    split3h<<<dim3((n4i + 255) / 256, 3), 256, 0, s0>>>(q, k, v, xqh, xkh, xvh, xql, xkl, xvl, n4i);
    conv4h<<<dim3((n4w + 255) / 256, 4), 256, 0, s0>>>(w_q, w_k, w_v, w_fc, wqh, wkh, wvh, wfh, n4w);

    // 2) projections (2-product fp16), then V transpose
    proj_gemm<<<dim3(DD / 128, M / 64, 3), 256, GM_SMEM, s0>>>(
        xqh, xql, xkh, xkl, xvh, xvl,
        wqh, wkh, wvh,
        qph, qpl, kph, kpl, vp);
    vtrans_f16<<<dim3(NN_ / 32, DD / 32, BB), dim3(32, 8), 0, s0>>>(vp, vth);

    // 3) fused attention (E + rowsum + feat fp16 hi/lo)
    fused_attn<<<dim3(NN_ / 128, BB * HH), 256, FU_SMEM, s0>>>(
        kph, kpl, qph, vth, eptr, rsum, fth, ftl);
    cudaEventRecord(ev_fused, s0);

    // 4) fork: attn_norm (DRAM-bound) on side stream, fc+LN (tensor) on main
    cudaStreamWaitEvent(s_side, ev_fused, 0);
    attn_norm<<<BB * HH * NN_, 256, 0, s_side>>>(eptr, rsum, attn);
    cudaEventRecord(ev_norm, s_side);

    fc_gemm<<<dim3(DD / 128, M / 64), 256, GM_SMEM, s0>>>(fth, ftl, wfh, out, q);
    layernorm_rows<<<M, 256, 0, s0>>>(out, gam, bet);

    // join: main stream waits for attn_norm completion
    cudaStreamWaitEvent(s0, ev_norm, 0);
}

// round 16
// speedup vs baseline: 1.0201x; 1.0201x over previous
#include <cuda_runtime.h>
#include <cuda_bf16.h>
#include <cuda_fp16.h>
#include <math.h>
#include <stdint.h>

#define BB 2
#define NN_ 4096
#define DD 512
#define HH 8
#define DK 64

// ---------------------------------------------------------------------------
// Scratch (device globals — no allocation allowed)
// ---------------------------------------------------------------------------
__device__ float g_vp[BB * NN_ * DD];
__device__ float g_rowsum[BB * HH * NN_];
__device__ __half g_e[(size_t)BB * HH * NN_ * NN_];      // unnormalized exp, fp16

__device__ __half g_xq_h[BB * NN_ * DD]; __device__ __half g_xq_l[BB * NN_ * DD];
__device__ __half g_xk_h[BB * NN_ * DD]; __device__ __half g_xk_l[BB * NN_ * DD];
__device__ __half g_xv_h[BB * NN_ * DD]; __device__ __half g_xv_l[BB * NN_ * DD];
__device__ __half g_wq_h[DD * DD];
__device__ __half g_wk_h[DD * DD];
__device__ __half g_wv_h[DD * DD];
__device__ __half g_wf_h[DD * DD];
__device__ __half g_qp_h[BB * NN_ * DD]; __device__ __half g_qp_l[BB * NN_ * DD];
__device__ __half g_kp_h[BB * NN_ * DD]; __device__ __half g_kp_l[BB * NN_ * DD];
__device__ __half g_vpt_h[BB * HH * DK * NN_];           // [bh, d, token] fp16
__device__ __half g_ft_h[BB * NN_ * DD]; __device__ __half g_ft_l[BB * NN_ * DD];

// ---------------------------------------------------------------------------
// PTX helpers
// ---------------------------------------------------------------------------
__device__ __forceinline__ uint32_t smem_u32(const void* p) {
    uint32_t a;
    asm("{ .reg .u64 t; cvta.to.shared.u64 t, %1; cvt.u32.u64 %0, t; }"
        : "=r"(a) : "l"(p));
    return a;
}

#define CP16(dst, src) \
    asm volatile("cp.async.cg.shared.global [%0], [%1], 16;" :: "r"(dst), "l"(src))
#define CP_COMMIT() asm volatile("cp.async.commit_group;" ::: "memory")
#define CP_WAIT0()  asm volatile("cp.async.wait_group 0;" ::: "memory")
#define CP_WAIT1()  asm volatile("cp.async.wait_group 1;" ::: "memory")

__device__ __forceinline__ void ldsm4(uint32_t& r0, uint32_t& r1, uint32_t& r2, uint32_t& r3,
                                      uint32_t addr) {
    asm volatile("ldmatrix.sync.aligned.m8n8.x4.shared.b16 {%0,%1,%2,%3}, [%4];"
                 : "=r"(r0), "=r"(r1), "=r"(r2), "=r"(r3) : "r"(addr));
}

__device__ __forceinline__ void mma16816h(float* c,
                                          uint32_t a0, uint32_t a1, uint32_t a2, uint32_t a3,
                                          uint32_t b0, uint32_t b1) {
    asm volatile(
        "mma.sync.aligned.m16n8k16.row.col.f32.f16.f16.f32 "
        "{%0,%1,%2,%3}, {%4,%5,%6,%7}, {%8,%9}, {%0,%1,%2,%3};"
        : "+f"(c[0]), "+f"(c[1]), "+f"(c[2]), "+f"(c[3])
        : "r"(a0), "r"(a1), "r"(a2), "r"(a3), "r"(b0), "r"(b1));
}

__device__ __forceinline__ void split1h(float x, __half& h, __half& l) {
    h = __float2half_rn(x);
    l = __float2half_rn(x - __half2float(h));
}

// fp32 -> fp16 hi/lo split (inputs q,k,v), merged 3-way
__global__ void split3h(const float* x0, const float* x1, const float* x2,
                        __half* h0, __half* h1, __half* h2,
                        __half* l0, __half* l1, __half* l2, int n4)
{
    int i = blockIdx.x * blockDim.x + threadIdx.x;
    if (i >= n4) return;
    int w = blockIdx.y;
    const float* x = (w == 0) ? x0 : (w == 1) ? x1 : x2;
    __half* hi = (w == 0) ? h0 : (w == 1) ? h1 : h2;
    __half* lo = (w == 0) ? l0 : (w == 1) ? l1 : l2;
    float4 v = reinterpret_cast<const float4*>(x)[i];
    __half h[4], l[4];
    split1h(v.x, h[0], l[0]); split1h(v.y, h[1], l[1]);
    split1h(v.z, h[2], l[2]); split1h(v.w, h[3], l[3]);
    uint2 ph, pl;
    ph.x = ((uint32_t)*(uint16_t*)&h[1] << 16) | *(uint16_t*)&h[0];
    ph.y = ((uint32_t)*(uint16_t*)&h[3] << 16) | *(uint16_t*)&h[2];
    pl.x = ((uint32_t)*(uint16_t*)&l[1] << 16) | *(uint16_t*)&l[0];
    pl.y = ((uint32_t)*(uint16_t*)&l[3] << 16) | *(uint16_t*)&l[2];
    reinterpret_cast<uint2*>(hi)[i] = ph;
    reinterpret_cast<uint2*>(lo)[i] = pl;
}

// fp32 -> fp16 (hi only) conversion for 4 weight matrices
__global__ void conv4h(const float* x0, const float* x1, const float* x2, const float* x3,
                       __half* h0, __half* h1, __half* h2, __half* h3, int n4)
{
    int i = blockIdx.x * blockDim.x + threadIdx.x;
    if (i >= n4) return;
    int w = blockIdx.y;
    const float* x = (w == 0) ? x0 : (w == 1) ? x1 : (w == 2) ? x2 : x3;
    __half* hi = (w == 0) ? h0 : (w == 1) ? h1 : (w == 2) ? h2 : h3;
    float4 v = reinterpret_cast<const float4*>(x)[i];
    __half2 a = __floats2half2_rn(v.x, v.y);
    __half2 b = __floats2half2_rn(v.z, v.w);
    uint2 p;
    p.x = *reinterpret_cast<uint32_t*>(&a);
    p.y = *reinterpret_cast<uint32_t*>(&b);
    reinterpret_cast<uint2*>(hi)[i] = p;
}

// vp [B, N, D] fp32 -> vpT fp16 [B*H, DK, N]
__global__ void vtrans_f16(const float* __restrict__ vp, __half* __restrict__ vt)
{
    __shared__ float tile[32][33];
    const int j0 = blockIdx.x * 32;
    const int c0 = blockIdx.y * 32;
    const int b  = blockIdx.z;
    const int tx = threadIdx.x, ty = threadIdx.y;
    for (int rr = ty; rr < 32; rr += 8)
        tile[rr][tx] = vp[((long long)(b * NN_ + j0 + rr)) * DD + c0 + tx];
    __syncthreads();
    for (int rr = ty; rr < 32; rr += 8) {
        int c = c0 + rr;
        int h = c >> 6, dl = c & 63;
        long long idx = ((long long)(b * HH + h) * DK + dl) * NN_ + j0 + tx;
        vt[idx] = __float2half_rn(tile[tx][rr]);
    }
}

// ---------------------------------------------------------------------------
// Shared GEMM mainloop: 2-product fp16 (A_hi + A_lo) x B_hi.
// BM=64, BN=128, BK=32, 3-stage cp.async pipeline with ONE barrier per step.
// smem/stage: A_hi 5120 + A_lo 5120 + B_hi 10240 = 20480; 3 stages = 60KB.
// ---------------------------------------------------------------------------
#define GM_SMEM 61440
#define GM_STG  20480u

__device__ __forceinline__ void gemm_mainloop(
    const __half* __restrict__ Ahi, const __half* __restrict__ Alo,
    const __half* __restrict__ Bhi,
    int m0, int n0, uint32_t sb, int tid, int wid, int lane,
    float acc[2][4][4])
{
    const int wm = (wid >> 2) * 32;
    const int wn = (wid & 3) * 32;

    auto load_stage = [&](int kt) {
        const int k0 = kt * 32;
        const uint32_t st = sb + (uint32_t)(kt % 3) * GM_STG;
        for (int i = tid; i < 1024; i += 256) {
            if (i < 512) {
                int t = (i >> 8) & 1, r = (i & 255) >> 2, c = i & 3;
                const __half* src = (t ? Alo : Ahi) + (long long)(m0 + r) * DD + k0 + c * 8;
                CP16(st + (uint32_t)t * 5120u + (uint32_t)(r * 80 + c * 16), (const char*)src);
            } else {
                int j = i - 512;
                int r = j >> 2, c = j & 3;
                const __half* src = Bhi + (long long)(n0 + r) * DD + k0 + c * 8;
                CP16(st + 10240u + (uint32_t)(r * 80 + c * 16), (const char*)src);
            }
        }
    };

    load_stage(0); CP_COMMIT();
    load_stage(1); CP_COMMIT();

    for (int kt = 0; kt < 16; kt++) {
        if (kt < 15) CP_WAIT1(); else CP_WAIT0();
        __syncthreads();                       // single barrier per step
        if (kt + 2 < 16) { load_stage(kt + 2); CP_COMMIT(); }
        const uint32_t st = sb + (uint32_t)(kt % 3) * GM_STG;
#pragma unroll
        for (int prod = 0; prod < 2; prod++) {
            const uint32_t Ab = st + ((prod == 1) ? 5120u : 0u);
            const uint32_t Bb = st + 10240u;
#pragma unroll
            for (int kc = 0; kc < 2; kc++) {
                const uint32_t colA = (uint32_t)(kc * 32 + ((lane >> 4) & 1) * 16);
                const uint32_t colB = (uint32_t)(kc * 32 + ((lane >> 3) & 1) * 16);
                uint32_t bf[8];
#pragma unroll
                for (int j = 0; j < 2; j++) {
                    int n = wn + j * 16 + ((lane >> 4) & 1) * 8 + (lane & 7);
                    ldsm4(bf[j * 4 + 0], bf[j * 4 + 1], bf[j * 4 + 2], bf[j * 4 + 3],
                          Bb + (uint32_t)(n * 80) + colB);
                }
#pragma unroll
                for (int mi = 0; mi < 2; mi++) {
                    uint32_t a0, a1, a2, a3;
                    int m = wm + mi * 16 + (lane & 15);
                    ldsm4(a0, a1, a2, a3, Ab + (uint32_t)(m * 80) + colA);
#pragma unroll
                    for (int j = 0; j < 2; j++) {
                        mma16816h(acc[mi][2 * j],     a0, a1, a2, a3, bf[j * 4 + 0], bf[j * 4 + 1]);
                        mma16816h(acc[mi][2 * j + 1], a0, a1, a2, a3, bf[j * 4 + 2], bf[j * 4 + 3]);
                    }
                }
            }
        }
    }
}

// ---------------------------------------------------------------------------
// Merged projection GEMM: grid (4, 128, 3). z=0 Q->fp16 hi/lo, z=1 K->fp16
// hi/lo, z=2 V->fp32.
// ---------------------------------------------------------------------------
__global__ void __launch_bounds__(256, 2)
proj_gemm(const __half* __restrict__ xqh, const __half* __restrict__ xql,
          const __half* __restrict__ xkh, const __half* __restrict__ xkl,
          const __half* __restrict__ xvh, const __half* __restrict__ xvl,
          const __half* __restrict__ wqh, const __half* __restrict__ wkh,
          const __half* __restrict__ wvh,
          __half* __restrict__ qph, __half* __restrict__ qpl,
          __half* __restrict__ kph, __half* __restrict__ kpl,
          float* __restrict__ vp)
{
    extern __shared__ char smem[];
    const int tid = threadIdx.x;
    const int wid = tid >> 5;
    const int lane = tid & 31;
    const uint32_t sb = smem_u32(smem);
    const int n0 = blockIdx.x * 128;
    const int m0 = blockIdx.y * 64;
    const int z = blockIdx.z;

    const __half *Ahi, *Alo, *Bhi;
    if (z == 0)      { Ahi = xqh; Alo = xql; Bhi = wqh; }
    else if (z == 1) { Ahi = xkh; Alo = xkl; Bhi = wkh; }
    else             { Ahi = xvh; Alo = xvl; Bhi = wvh; }

    float acc[2][4][4];
#pragma unroll
    for (int i = 0; i < 2; i++)
#pragma unroll
        for (int j = 0; j < 4; j++)
#pragma unroll
            for (int c = 0; c < 4; c++) acc[i][j][c] = 0.0f;

    gemm_mainloop(Ahi, Alo, Bhi, m0, n0, sb, tid, wid, lane, acc);

    const int wm = (wid >> 2) * 32;
    const int wn = (wid & 3) * 32;
#pragma unroll
    for (int mi = 0; mi < 2; mi++) {
#pragma unroll
        for (int ni = 0; ni < 4; ni++) {
            int r  = wm + mi * 16 + (lane >> 2);
            int cc = wn + ni * 8 + (lane & 3) * 2;
#pragma unroll
            for (int half = 0; half < 2; half++) {
                int row = m0 + r + half * 8;
                int col = n0 + cc;
                float v0 = acc[mi][ni][half * 2 + 0];
                float v1 = acc[mi][ni][half * 2 + 1];
                if (z < 2) {
                    __half h0, l0, h1, l1;
                    split1h(v0, h0, l0); split1h(v1, h1, l1);
                    uint32_t ph = ((uint32_t)*(uint16_t*)&h1 << 16) | *(uint16_t*)&h0;
                    uint32_t pl = ((uint32_t)*(uint16_t*)&l1 << 16) | *(uint16_t*)&l0;
                    __half* Ch = z ? kph : qph;
                    __half* Cl = z ? kpl : qpl;
                    *reinterpret_cast<uint32_t*>(Ch + (long long)row * DD + col) = ph;
                    *reinterpret_cast<uint32_t*>(Cl + (long long)row * DD + col) = pl;
                } else {
                    float2 o; o.x = v0; o.y = v1;
                    *reinterpret_cast<float2*>(vp + (long long)row * DD + col) = o;
                }
            }
        }
    }
}

// ---------------------------------------------------------------------------
// fc GEMM + residual
// ---------------------------------------------------------------------------
__global__ void __launch_bounds__(256, 2)
fc_gemm(const __half* __restrict__ Ahi, const __half* __restrict__ Alo,
        const __half* __restrict__ Bhi,
        float* __restrict__ Cf, const float* __restrict__ R)
{
    extern __shared__ char smem[];
    const int tid = threadIdx.x;
    const int wid = tid >> 5;
    const int lane = tid & 31;
    const uint32_t sb = smem_u32(smem);
    const int n0 = blockIdx.x * 128;
    const int m0 = blockIdx.y * 64;

    float acc[2][4][4];
#pragma unroll
    for (int i = 0; i < 2; i++)
#pragma unroll
        for (int j = 0; j < 4; j++)
#pragma unroll
            for (int c = 0; c < 4; c++) acc[i][j][c] = 0.0f;

    gemm_mainloop(Ahi, Alo, Bhi, m0, n0, sb, tid, wid, lane, acc);

    const int wm = (wid >> 2) * 32;
    const int wn = (wid & 3) * 32;
#pragma unroll
    for (int mi = 0; mi < 2; mi++) {
#pragma unroll
        for (int ni = 0; ni < 4; ni++) {
            int r  = wm + mi * 16 + (lane >> 2);
            int cc = wn + ni * 8 + (lane & 3) * 2;
#pragma unroll
            for (int half = 0; half < 2; half++) {
                int row = m0 + r + half * 8;
                int col = n0 + cc;
                float v0 = acc[mi][ni][half * 2 + 0];
                float v1 = acc[mi][ni][half * 2 + 1];
                float2 r2 = *reinterpret_cast<const float2*>(R + (long long)row * DD + col);
                float2 o; o.x = v0 + r2.x; o.y = v1 + r2.y;
                *reinterpret_cast<float2*>(Cf + (long long)row * DD + col) = o;
            }
        }
    }
}

// ---------------------------------------------------------------------------
// Fused attention, single pass: 2-product fp16 scores, E scratch + rowsum
// + feat fp16 hi/lo. 3-stage Q/V pipeline, ONE barrier per nb step.
// smem: K 36KB + Q 3x9KB + V 3x9KB = 90KB -> 2 CTAs/SM.
// ---------------------------------------------------------------------------
#define FU_SMEM 92160
#define FU_KHI 0u
#define FU_KLO 18432u
#define FU_Q0  36864u
#define FU_QST 9216u
#define FU_V0  64512u
#define FU_VST 9216u

__global__ void __launch_bounds__(256, 2)
fused_attn(const __half* __restrict__ Khi, const __half* __restrict__ Klo,
           const __half* __restrict__ Qhi,
           const __half* __restrict__ Vh,
           __half* __restrict__ E, float* __restrict__ rowsum,
           __half* __restrict__ Fhi, __half* __restrict__ Flo)
{
    extern __shared__ char smem[];
    const int tid = threadIdx.x;
    const int wid = tid >> 5;
    const int lane = tid & 31;
    const uint32_t sb = smem_u32(smem);

    const int m0 = blockIdx.x * 128;
    const int bh = blockIdx.y;
    const int b = bh >> 3, h = bh & 7;
    const long long arow = (long long)(b * NN_ + m0);
    const int coff = h * DK;
    const long long vrow = (long long)bh * DK;

    auto load_QV = [&](int nb) {
        const int s = nb % 3;
        const long long brow = (long long)b * NN_ + (long long)nb * 64;
        const uint32_t qst = sb + FU_Q0 + (uint32_t)s * FU_QST;
        const uint32_t vst = sb + FU_V0 + (uint32_t)s * FU_VST;
        for (int i = tid; i < 1024; i += 256) {
            int t = i >> 9, r = (i & 511) >> 3, c = i & 7;
            if (t == 0) {
                CP16(qst + (uint32_t)(r * 144 + c * 16),
                     (const char*)(Qhi + (brow + r) * DD + coff + c * 8));
            } else {
                CP16(vst + (uint32_t)(r * 144 + c * 16),
                     (const char*)(Vh + (vrow + r) * NN_ + nb * 64 + c * 8));
            }
        }
    };

    // K resident + first Q/V stage in group 0
    for (int i = tid; i < 2048; i += 256) {
        int t = i >> 10, r = (i & 1023) >> 3, c = i & 7;
        const __half* src = (t ? Klo : Khi) + (arow + r) * DD + coff + c * 8;
        CP16(sb + (uint32_t)t * 18432u + (uint32_t)(r * 144 + c * 16), (const char*)src);
    }
    load_QV(0); CP_COMMIT();
    load_QV(1); CP_COMMIT();

    const int gid = lane >> 2, tig = lane & 3;
    const long long ebase = (long long)bh * NN_ * NN_;
    const int mrow = m0 + wid * 16 + gid;

    float rs0 = 0.0f, rs1 = 0.0f;
    float facc[8][4];
#pragma unroll
    for (int i = 0; i < 8; i++)
#pragma unroll
        for (int c = 0; c < 4; c++) facc[i][c] = 0.0f;

    for (int nb = 0; nb < 64; nb++) {
        if (nb < 63) CP_WAIT1(); else CP_WAIT0();
        __syncthreads();                       // single barrier per step
        if (nb + 2 < 64) { load_QV(nb + 2); CP_COMMIT(); }

        const uint32_t Qst = sb + FU_Q0 + (uint32_t)(nb % 3) * FU_QST;
        const uint32_t Vst = sb + FU_V0 + (uint32_t)(nb % 3) * FU_VST;

        float sacc[8][4];
#pragma unroll
        for (int i = 0; i < 8; i++)
#pragma unroll
            for (int c = 0; c < 4; c++) sacc[i][c] = 0.0f;

#pragma unroll
        for (int prod = 0; prod < 2; prod++) {
            const uint32_t Ab = sb + ((prod == 1) ? FU_KLO : FU_KHI);
#pragma unroll
            for (int kc = 0; kc < 4; kc++) {
                const uint32_t colA = (uint32_t)(kc * 32 + ((lane >> 4) & 1) * 16);
                const uint32_t colB = (uint32_t)(kc * 32 + ((lane >> 3) & 1) * 16);
                uint32_t a0, a1, a2, a3;
                ldsm4(a0, a1, a2, a3,
                      Ab + (uint32_t)((wid * 16 + (lane & 15)) * 144) + colA);
#pragma unroll
                for (int j = 0; j < 4; j++) {
                    int n = j * 16 + ((lane >> 4) & 1) * 8 + (lane & 7);
                    uint32_t q0, q1, q2, q3;
                    ldsm4(q0, q1, q2, q3, Qst + (uint32_t)(n * 144) + colB);
                    mma16816h(sacc[2 * j],     a0, a1, a2, a3, q0, q1);
                    mma16816h(sacc[2 * j + 1], a0, a1, a2, a3, q2, q3);
                }
            }
        }

#pragma unroll
        for (int kch = 0; kch < 4; kch++) {
            uint32_t a0, a1, a2, a3;
#pragma unroll
            for (int jj = 0; jj < 2; jj++) {
                int j = 2 * kch + jj;
                float e0 = __expf(0.125f * sacc[j][0]);
                float e1 = __expf(0.125f * sacc[j][1]);
                float e2 = __expf(0.125f * sacc[j][2]);
                float e3 = __expf(0.125f * sacc[j][3]);
                rs0 += e0 + e1;
                rs1 += e2 + e3;
                __half2 h01 = __floats2half2_rn(e0, e1);
                __half2 h23 = __floats2half2_rn(e2, e3);
                long long colg = (long long)nb * 64 + j * 8 + tig * 2;
                *reinterpret_cast<uint32_t*>(E + ebase + (long long)mrow * NN_ + colg) =
                    *reinterpret_cast<uint32_t*>(&h01);
                *reinterpret_cast<uint32_t*>(E + ebase + (long long)(mrow + 8) * NN_ + colg) =
                    *reinterpret_cast<uint32_t*>(&h23);
                if (jj == 0) { a0 = *reinterpret_cast<uint32_t*>(&h01);
                               a1 = *reinterpret_cast<uint32_t*>(&h23); }
                else         { a2 = *reinterpret_cast<uint32_t*>(&h01);
                               a3 = *reinterpret_cast<uint32_t*>(&h23); }
            }
            const uint32_t colV = (uint32_t)(kch * 32 + ((lane >> 3) & 1) * 16);
#pragma unroll
            for (int vj = 0; vj < 4; vj++) {
                int n = vj * 16 + ((lane >> 4) & 1) * 8 + (lane & 7);
                uint32_t v0, v1, v2, v3;
                ldsm4(v0, v1, v2, v3, Vst + (uint32_t)(n * 144) + colV);
                mma16816h(facc[2 * vj],     a0, a1, a2, a3, v0, v1);
                mma16816h(facc[2 * vj + 1], a0, a1, a2, a3, v2, v3);
            }
        }
    }

    rs0 += __shfl_xor_sync(~0u, rs0, 1);
    rs0 += __shfl_xor_sync(~0u, rs0, 2);
    rs1 += __shfl_xor_sync(~0u, rs1, 1);
    rs1 += __shfl_xor_sync(~0u, rs1, 2);
    const float inv0 = __frcp_rn(rs0);
    const float inv1 = __frcp_rn(rs1);
    if (tig == 0) {
        rowsum[(long long)bh * NN_ + mrow]     = rs0;
        rowsum[(long long)bh * NN_ + mrow + 8] = rs1;
    }

#pragma unroll
    for (int n8 = 0; n8 < 8; n8++) {
        int col = h * DK + n8 * 8 + tig * 2;
#pragma unroll
        for (int half = 0; half < 2; half++) {
            long long row = (long long)(b * NN_ + mrow + half * 8);
            float inv = half ? inv1 : inv0;
            float v0 = facc[n8][half * 2 + 0] * inv;
            float v1 = facc[n8][half * 2 + 1] * inv;
            __half h0, l0, h1, l1;
            split1h(v0, h0, l0); split1h(v1, h1, l1);
            uint32_t ph = ((uint32_t)*(uint16_t*)&h1 << 16) | *(uint16_t*)&h0;
            uint32_t pl = ((uint32_t)*(uint16_t*)&l1 << 16) | *(uint16_t*)&l0;
            *reinterpret_cast<uint32_t*>(Fhi + row * DD + col) = ph;
            *reinterpret_cast<uint32_t*>(Flo + row * DD + col) = pl;
        }
    }
}

// ---------------------------------------------------------------------------
// attn_norm: attn[row, :] = float(E[row, :]) * rcp(rowsum[row])
// ---------------------------------------------------------------------------
__global__ void __launch_bounds__(256)
attn_norm(const __half* __restrict__ E, const float* __restrict__ rowsum,
          float* __restrict__ A)
{
    const long long row = blockIdx.x;
    const float inv = __frcp_rn(rowsum[row]);
    const uint2* pe = reinterpret_cast<const uint2*>(E + row * (long long)NN_);
    float4* pa = reinterpret_cast<float4*>(A + row * (long long)NN_);
    const int t = threadIdx.x;
#pragma unroll
    for (int i = 0; i < 4; i++) {
        uint2 u = pe[t + i * 256];
        __half2 a = *reinterpret_cast<__half2*>(&u.x);
        __half2 bq = *reinterpret_cast<__half2*>(&u.y);
        float2 fa = __half22float2(a);
        float2 fb = __half22float2(bq);
        float4 o;
        o.x = fa.x * inv; o.y = fa.y * inv;
        o.z = fb.x * inv; o.w = fb.y * inv;
        pa[t + i * 256] = o;
    }
}

// ---------------------------------------------------------------------------
// In-place row LayerNorm
// ---------------------------------------------------------------------------
__global__ void layernorm_rows(float* __restrict__ y,
                               const float* __restrict__ gamma,
                               const float* __restrict__ beta)
{
    const long long base = (long long)blockIdx.x * DD;
    const int t = threadIdx.x;
    const int lane = t & 31, warp = t >> 5;
    __shared__ float red[32];

    float x0 = y[base + t];
    float x1 = y[base + t + 256];

    float s = x0 + x1;
#pragma unroll
    for (int o = 16; o > 0; o >>= 1) s += __shfl_xor_sync(~0u, s, o);
    if (lane == 0) red[warp] = s;
    __syncthreads();
    if (warp == 0) {
        float x = (lane < 8) ? red[lane] : 0.0f;
#pragma unroll
        for (int o = 16; o > 0; o >>= 1) x += __shfl_xor_sync(~0u, x, o);
        if (lane == 0) red[0] = x;
    }
    __syncthreads();
    const float mu = red[0] * (1.0f / DD);
    __syncthreads();

    const float d0 = x0 - mu, d1 = x1 - mu;
    float v = d0 * d0 + d1 * d1;
#pragma unroll
    for (int o = 16; o > 0; o >>= 1) v += __shfl_xor_sync(~0u, v, o);
    if (lane == 0) red[warp] = v;
    __syncthreads();
    if (warp == 0) {
        float x = (lane < 8) ? red[lane] : 0.0f;
#pragma unroll
        for (int o = 16; o > 0; o >>= 1) x += __shfl_xor_sync(~0u, x, o);
        if (lane == 0) red[0] = x;
    }
    __syncthreads();
    const float r = rsqrtf(red[0] * (1.0f / DD) + 1e-5f);

    y[base + t]       = d0 * r * gamma[t]       + beta[t];
    y[base + t + 256] = d1 * r * gamma[t + 256] + beta[t + 256];
}

// ---------------------------------------------------------------------------
extern "C" void kernel_launch(void* const* d_in, const int* in_sizes, int n_in,
                              void* d_out, int out_size)
{
    const float* q    = (const float*)d_in[0];
    const float* k    = (const float*)d_in[1];
    const float* v    = (const float*)d_in[2];
    const float* w_q  = (const float*)d_in[3];
    const float* w_k  = (const float*)d_in[4];
    const float* w_v  = (const float*)d_in[5];
    const float* w_fc = (const float*)d_in[6];
    const float* gam  = (const float*)d_in[7];
    const float* bet  = (const float*)d_in[8];

    float* out  = (float*)d_out;                          // [B,N,D]
    float* attn = out + (long long)BB * NN_ * DD;         // [B,H,N,N]

    float *vp, *rsum;
    __half* eptr;
    cudaGetSymbolAddress((void**)&vp,   g_vp);
    cudaGetSymbolAddress((void**)&rsum, g_rowsum);
    cudaGetSymbolAddress((void**)&eptr, g_e);
    __half *xqh, *xql, *xkh, *xkl, *xvh, *xvl;
    __half *wqh, *wkh, *wvh, *wfh;
    __half *qph, *qpl, *kph, *kpl, *vth, *fth, *ftl;
    cudaGetSymbolAddress((void**)&xqh, g_xq_h); cudaGetSymbolAddress((void**)&xql, g_xq_l);
    cudaGetSymbolAddress((void**)&xkh, g_xk_h); cudaGetSymbolAddress((void**)&xkl, g_xk_l);
    cudaGetSymbolAddress((void**)&xvh, g_xv_h); cudaGetSymbolAddress((void**)&xvl, g_xv_l);
    cudaGetSymbolAddress((void**)&wqh, g_wq_h);
    cudaGetSymbolAddress((void**)&wkh, g_wk_h);
    cudaGetSymbolAddress((void**)&wvh, g_wv_h);
    cudaGetSymbolAddress((void**)&wfh, g_wf_h);
    cudaGetSymbolAddress((void**)&qph, g_qp_h); cudaGetSymbolAddress((void**)&qpl, g_qp_l);
    cudaGetSymbolAddress((void**)&kph, g_kp_h); cudaGetSymbolAddress((void**)&kpl, g_kp_l);
    cudaGetSymbolAddress((void**)&vth, g_vpt_h);
    cudaGetSymbolAddress((void**)&fth, g_ft_h); cudaGetSymbolAddress((void**)&ftl, g_ft_l);

    cudaFuncSetAttribute(proj_gemm,  cudaFuncAttributeMaxDynamicSharedMemorySize, GM_SMEM);
    cudaFuncSetAttribute(fc_gemm,    cudaFuncAttributeMaxDynamicSharedMemorySize, GM_SMEM);
    cudaFuncSetAttribute(fused_attn, cudaFuncAttributeMaxDynamicSharedMemorySize, FU_SMEM);

    const int M = BB * NN_;          // 8192
    const int n4i = M * DD / 4;
    const int n4w = DD * DD / 4;

    // 1) splits/conversions
    split3h<<<dim3((n4i + 255) / 256, 3), 256>>>(q, k, v, xqh, xkh, xvh, xql, xkl, xvl, n4i);
    conv4h<<<dim3((n4w + 255) / 256, 4), 256>>>(w_q, w_k, w_v, w_fc, wqh, wkh, wvh, wfh, n4w);

    // 2) projections (2-product fp16), then V transpose
    proj_gemm<<<dim3(DD / 128, M / 64, 3), 256, GM_SMEM>>>(
        xqh, xql, xkh, xkl, xvh, xvl,
        wqh, wkh, wvh,
        qph, qpl, kph, kpl, vp);
    vtrans_f16<<<dim3(NN_ / 32, DD / 32, BB), dim3(32, 8)>>>(vp, vth);

    // 3) fused attention (E + rowsum + feat fp16 hi/lo)
    fused_attn<<<dim3(NN_ / 128, BB * HH), 256, FU_SMEM>>>(
        kph, kpl, qph, vth, eptr, rsum, fth, ftl);

    // 4) normalize attn into output region
    attn_norm<<<BB * HH * NN_, 256>>>(eptr, rsum, attn);

    // 5) fc + residual
    fc_gemm<<<dim3(DD / 128, M / 64), 256, GM_SMEM>>>(fth, ftl, wfh, out, q);

    // 6) LayerNorm
    layernorm_rows<<<M, 256>>>(out, gam, bet);
}

// round 17
// speedup vs baseline: 1.1125x; 1.0906x over previous
#include <cuda_runtime.h>
#include <cuda_bf16.h>
#include <cuda_fp16.h>
#include <math.h>
#include <stdint.h>

#define BB 2
#define NN_ 4096
#define DD 512
#define HH 8
#define DK 64

// ---------------------------------------------------------------------------
// Scratch (device globals — no allocation allowed)
// ---------------------------------------------------------------------------
__device__ float g_rowsum[BB * HH * NN_];
__device__ __half g_e[(size_t)BB * HH * NN_ * NN_];      // unnormalized exp, fp16

__device__ __half g_xq_h[BB * NN_ * DD]; __device__ __half g_xq_l[BB * NN_ * DD];
__device__ __half g_xk_h[BB * NN_ * DD]; __device__ __half g_xk_l[BB * NN_ * DD];
__device__ __half g_xv_h[BB * NN_ * DD]; __device__ __half g_xv_l[BB * NN_ * DD];
__device__ __half g_wq_h[DD * DD];
__device__ __half g_wk_h[DD * DD];
__device__ __half g_wv_h[DD * DD];
__device__ __half g_wf_h[DD * DD];
__device__ __half g_qp_h[BB * NN_ * DD];
__device__ __half g_kp_h[BB * NN_ * DD];
__device__ __half g_vpt_h[BB * HH * DK * NN_];           // [bh, d, token] fp16
__device__ __half g_ft_h[BB * NN_ * DD]; __device__ __half g_ft_l[BB * NN_ * DD];

// ---------------------------------------------------------------------------
// PTX helpers
// ---------------------------------------------------------------------------
__device__ __forceinline__ uint32_t smem_u32(const void* p) {
    uint32_t a;
    asm("{ .reg .u64 t; cvta.to.shared.u64 t, %1; cvt.u32.u64 %0, t; }"
        : "=r"(a) : "l"(p));
    return a;
}

#define CP16(dst, src) \
    asm volatile("cp.async.cg.shared.global [%0], [%1], 16;" :: "r"(dst), "l"(src))
#define CP_COMMIT() asm volatile("cp.async.commit_group;" ::: "memory")
#define CP_WAIT0()  asm volatile("cp.async.wait_group 0;" ::: "memory")
#define CP_WAIT1()  asm volatile("cp.async.wait_group 1;" ::: "memory")

__device__ __forceinline__ void ldsm4(uint32_t& r0, uint32_t& r1, uint32_t& r2, uint32_t& r3,
                                      uint32_t addr) {
    asm volatile("ldmatrix.sync.aligned.m8n8.x4.shared.b16 {%0,%1,%2,%3}, [%4];"
                 : "=r"(r0), "=r"(r1), "=r"(r2), "=r"(r3) : "r"(addr));
}

__device__ __forceinline__ void mma16816h(float* c,
                                          uint32_t a0, uint32_t a1, uint32_t a2, uint32_t a3,
                                          uint32_t b0, uint32_t b1) {
    asm volatile(
        "mma.sync.aligned.m16n8k16.row.col.f32.f16.f16.f32 "
        "{%0,%1,%2,%3}, {%4,%5,%6,%7}, {%8,%9}, {%0,%1,%2,%3};"
        : "+f"(c[0]), "+f"(c[1]), "+f"(c[2]), "+f"(c[3])
        : "r"(a0), "r"(a1), "r"(a2), "r"(a3), "r"(b0), "r"(b1));
}

__device__ __forceinline__ void split1h(float x, __half& h, __half& l) {
    h = __float2half_rn(x);
    l = __float2half_rn(x - __half2float(h));
}

// fp32 -> fp16 hi/lo split (inputs q,k,v), merged 3-way
__global__ void split3h(const float* x0, const float* x1, const float* x2,
                        __half* h0, __half* h1, __half* h2,
                        __half* l0, __half* l1, __half* l2, int n4)
{
    int i = blockIdx.x * blockDim.x + threadIdx.x;
    if (i >= n4) return;
    int w = blockIdx.y;
    const float* x = (w == 0) ? x0 : (w == 1) ? x1 : x2;
    __half* hi = (w == 0) ? h0 : (w == 1) ? h1 : h2;
    __half* lo = (w == 0) ? l0 : (w == 1) ? l1 : l2;
    float4 v = reinterpret_cast<const float4*>(x)[i];
    __half h[4], l[4];
    split1h(v.x, h[0], l[0]); split1h(v.y, h[1], l[1]);
    split1h(v.z, h[2], l[2]); split1h(v.w, h[3], l[3]);
    uint2 ph, pl;
    ph.x = ((uint32_t)*(uint16_t*)&h[1] << 16) | *(uint16_t*)&h[0];
    ph.y = ((uint32_t)*(uint16_t*)&h[3] << 16) | *(uint16_t*)&h[2];
    pl.x = ((uint32_t)*(uint16_t*)&l[1] << 16) | *(uint16_t*)&l[0];
    pl.y = ((uint32_t)*(uint16_t*)&l[3] << 16) | *(uint16_t*)&l[2];
    reinterpret_cast<uint2*>(hi)[i] = ph;
    reinterpret_cast<uint2*>(lo)[i] = pl;
}

// fp32 -> fp16 (hi only) conversion for 4 weight matrices
__global__ void conv4h(const float* x0, const float* x1, const float* x2, const float* x3,
                       __half* h0, __half* h1, __half* h2, __half* h3, int n4)
{
    int i = blockIdx.x * blockDim.x + threadIdx.x;
    if (i >= n4) return;
    int w = blockIdx.y;
    const float* x = (w == 0) ? x0 : (w == 1) ? x1 : (w == 2) ? x2 : x3;
    __half* hi = (w == 0) ? h0 : (w == 1) ? h1 : (w == 2) ? h2 : h3;
    float4 v = reinterpret_cast<const float4*>(x)[i];
    __half2 a = __floats2half2_rn(v.x, v.y);
    __half2 b = __floats2half2_rn(v.z, v.w);
    uint2 p;
    p.x = *reinterpret_cast<uint32_t*>(&a);
    p.y = *reinterpret_cast<uint32_t*>(&b);
    reinterpret_cast<uint2*>(hi)[i] = p;
}

// ---------------------------------------------------------------------------
// Shared GEMM mainloop: 2-product fp16 (A_hi + A_lo) x B_hi.
// BM=64, BN=128, BK=32, 3-stage cp.async pipeline, ONE barrier per step.
// ---------------------------------------------------------------------------
#define GM_SMEM 61440
#define GM_STG  20480u

__device__ __forceinline__ void gemm_mainloop(
    const __half* __restrict__ Ahi, const __half* __restrict__ Alo,
    const __half* __restrict__ Bhi,
    int m0, int n0, uint32_t sb, int tid, int wid, int lane,
    float acc[2][4][4])
{
    const int wm = (wid >> 2) * 32;
    const int wn = (wid & 3) * 32;

    auto load_stage = [&](int kt) {
        const int k0 = kt * 32;
        const uint32_t st = sb + (uint32_t)(kt % 3) * GM_STG;
        for (int i = tid; i < 1024; i += 256) {
            if (i < 512) {
                int t = (i >> 8) & 1, r = (i & 255) >> 2, c = i & 3;
                const __half* src = (t ? Alo : Ahi) + (long long)(m0 + r) * DD + k0 + c * 8;
                CP16(st + (uint32_t)t * 5120u + (uint32_t)(r * 80 + c * 16), (const char*)src);
            } else {
                int j = i - 512;
                int r = j >> 2, c = j & 3;
                const __half* src = Bhi + (long long)(n0 + r) * DD + k0 + c * 8;
                CP16(st + 10240u + (uint32_t)(r * 80 + c * 16), (const char*)src);
            }
        }
    };

    load_stage(0); CP_COMMIT();
    load_stage(1); CP_COMMIT();

    for (int kt = 0; kt < 16; kt++) {
        if (kt < 15) CP_WAIT1(); else CP_WAIT0();
        __syncthreads();
        if (kt + 2 < 16) { load_stage(kt + 2); CP_COMMIT(); }
        const uint32_t st = sb + (uint32_t)(kt % 3) * GM_STG;
#pragma unroll
        for (int prod = 0; prod < 2; prod++) {
            const uint32_t Ab = st + ((prod == 1) ? 5120u : 0u);
            const uint32_t Bb = st + 10240u;
#pragma unroll
            for (int kc = 0; kc < 2; kc++) {
                const uint32_t colA = (uint32_t)(kc * 32 + ((lane >> 4) & 1) * 16);
                const uint32_t colB = (uint32_t)(kc * 32 + ((lane >> 3) & 1) * 16);
                uint32_t bf[8];
#pragma unroll
                for (int j = 0; j < 2; j++) {
                    int n = wn + j * 16 + ((lane >> 4) & 1) * 8 + (lane & 7);
                    ldsm4(bf[j * 4 + 0], bf[j * 4 + 1], bf[j * 4 + 2], bf[j * 4 + 3],
                          Bb + (uint32_t)(n * 80) + colB);
                }
#pragma unroll
                for (int mi = 0; mi < 2; mi++) {
                    uint32_t a0, a1, a2, a3;
                    int m = wm + mi * 16 + (lane & 15);
                    ldsm4(a0, a1, a2, a3, Ab + (uint32_t)(m * 80) + colA);
#pragma unroll
                    for (int j = 0; j < 2; j++) {
                        mma16816h(acc[mi][2 * j],     a0, a1, a2, a3, bf[j * 4 + 0], bf[j * 4 + 1]);
                        mma16816h(acc[mi][2 * j + 1], a0, a1, a2, a3, bf[j * 4 + 2], bf[j * 4 + 3]);
                    }
                }
            }
        }
    }
}

// ---------------------------------------------------------------------------
// Merged projection GEMM: grid (4, 128, 3).
// z=0 Q -> fp16 hi only; z=1 K -> fp16 hi only;
// z=2 V -> fp16 TRANSPOSED directly into vt [bh, d, token].
// ---------------------------------------------------------------------------
__global__ void __launch_bounds__(256, 2)
proj_gemm(const __half* __restrict__ xqh, const __half* __restrict__ xql,
          const __half* __restrict__ xkh, const __half* __restrict__ xkl,
          const __half* __restrict__ xvh, const __half* __restrict__ xvl,
          const __half* __restrict__ wqh, const __half* __restrict__ wkh,
          const __half* __restrict__ wvh,
          __half* __restrict__ qph, __half* __restrict__ kph,
          __half* __restrict__ vt)
{
    extern __shared__ char smem[];
    const int tid = threadIdx.x;
    const int wid = tid >> 5;
    const int lane = tid & 31;
    const uint32_t sb = smem_u32(smem);
    const int n0 = blockIdx.x * 128;
    const int m0 = blockIdx.y * 64;
    const int z = blockIdx.z;

    const __half *Ahi, *Alo, *Bhi;
    if (z == 0)      { Ahi = xqh; Alo = xql; Bhi = wqh; }
    else if (z == 1) { Ahi = xkh; Alo = xkl; Bhi = wkh; }
    else             { Ahi = xvh; Alo = xvl; Bhi = wvh; }

    float acc[2][4][4];
#pragma unroll
    for (int i = 0; i < 2; i++)
#pragma unroll
        for (int j = 0; j < 4; j++)
#pragma unroll
            for (int c = 0; c < 4; c++) acc[i][j][c] = 0.0f;

    gemm_mainloop(Ahi, Alo, Bhi, m0, n0, sb, tid, wid, lane, acc);

    const int wm = (wid >> 2) * 32;
    const int wn = (wid & 3) * 32;
#pragma unroll
    for (int mi = 0; mi < 2; mi++) {
#pragma unroll
        for (int ni = 0; ni < 4; ni++) {
            int r  = wm + mi * 16 + (lane >> 2);
            int cc = wn + ni * 8 + (lane & 3) * 2;
#pragma unroll
            for (int half = 0; half < 2; half++) {
                int row = m0 + r + half * 8;       // global token row [0, 8192)
                int col = n0 + cc;                 // dim [0, 512)
                float v0 = acc[mi][ni][half * 2 + 0];
                float v1 = acc[mi][ni][half * 2 + 1];
                if (z < 2) {
                    __half2 h01 = __floats2half2_rn(v0, v1);
                    __half* Ch = z ? kph : qph;
                    *reinterpret_cast<uint32_t*>(Ch + (long long)row * DD + col) =
                        *reinterpret_cast<uint32_t*>(&h01);
                } else {
                    // transposed V store: vt[(b*H + h)*DK + d][tok]
                    int bb = row >> 12;            // /4096
                    int tok = row & 4095;
                    int hh = col >> 6, dl = col & 63;
                    long long base0 = ((long long)((bb * HH + hh) * DK + dl)) * NN_ + tok;
                    vt[base0]       = __float2half_rn(v0);
                    vt[base0 + NN_] = __float2half_rn(v1);   // dl+1 < 64 (cc even)
                }
            }
        }
    }
}

// ---------------------------------------------------------------------------
// fc GEMM + residual
// ---------------------------------------------------------------------------
__global__ void __launch_bounds__(256, 2)
fc_gemm(const __half* __restrict__ Ahi, const __half* __restrict__ Alo,
        const __half* __restrict__ Bhi,
        float* __restrict__ Cf, const float* __restrict__ R)
{
    extern __shared__ char smem[];
    const int tid = threadIdx.x;
    const int wid = tid >> 5;
    const int lane = tid & 31;
    const uint32_t sb = smem_u32(smem);
    const int n0 = blockIdx.x * 128;
    const int m0 = blockIdx.y * 64;

    float acc[2][4][4];
#pragma unroll
    for (int i = 0; i < 2; i++)
#pragma unroll
        for (int j = 0; j < 4; j++)
#pragma unroll
            for (int c = 0; c < 4; c++) acc[i][j][c] = 0.0f;

    gemm_mainloop(Ahi, Alo, Bhi, m0, n0, sb, tid, wid, lane, acc);

    const int wm = (wid >> 2) * 32;
    const int wn = (wid & 3) * 32;
#pragma unroll
    for (int mi = 0; mi < 2; mi++) {
#pragma unroll
        for (int ni = 0; ni < 4; ni++) {
            int r  = wm + mi * 16 + (lane >> 2);
            int cc = wn + ni * 8 + (lane & 3) * 2;
#pragma unroll
            for (int half = 0; half < 2; half++) {
                int row = m0 + r + half * 8;
                int col = n0 + cc;
                float v0 = acc[mi][ni][half * 2 + 0];
                float v1 = acc[mi][ni][half * 2 + 1];
                float2 r2 = *reinterpret_cast<const float2*>(R + (long long)row * DD + col);
                float2 o; o.x = v0 + r2.x; o.y = v1 + r2.y;
                *reinterpret_cast<float2*>(Cf + (long long)row * DD + col) = o;
            }
        }
    }
}

// ---------------------------------------------------------------------------
// Fused attention: SINGLE fp16 product scores S = K_hi @ Q_hi^T,
// e = exp(0.125 S) -> fp16 -> E scratch + P@V (fp16), feat fp16 hi/lo out.
// 3-stage Q/V pipeline, ONE barrier per nb step.
// smem: K 18KB + Q 3x9KB + V 3x9KB = 72KB -> 2 CTAs/SM.
// ---------------------------------------------------------------------------
#define FU_SMEM 73728
#define FU_Q0  18432u
#define FU_QST 9216u
#define FU_V0  46080u
#define FU_VST 9216u

__global__ void __launch_bounds__(256, 2)
fused_attn(const __half* __restrict__ Khi,
           const __half* __restrict__ Qhi,
           const __half* __restrict__ Vh,
           __half* __restrict__ E, float* __restrict__ rowsum,
           __half* __restrict__ Fhi, __half* __restrict__ Flo)
{
    extern __shared__ char smem[];
    const int tid = threadIdx.x;
    const int wid = tid >> 5;
    const int lane = tid & 31;
    const uint32_t sb = smem_u32(smem);

    const int m0 = blockIdx.x * 128;
    const int bh = blockIdx.y;
    const int b = bh >> 3, h = bh & 7;
    const long long arow = (long long)(b * NN_ + m0);
    const int coff = h * DK;
    const long long vrow = (long long)bh * DK;

    auto load_QV = [&](int nb) {
        const int s = nb % 3;
        const long long brow = (long long)b * NN_ + (long long)nb * 64;
        const uint32_t qst = sb + FU_Q0 + (uint32_t)s * FU_QST;
        const uint32_t vst = sb + FU_V0 + (uint32_t)s * FU_VST;
        for (int i = tid; i < 1024; i += 256) {
            int t = i >> 9, r = (i & 511) >> 3, c = i & 7;
            if (t == 0) {
                CP16(qst + (uint32_t)(r * 144 + c * 16),
                     (const char*)(Qhi + (brow + r) * DD + coff + c * 8));
            } else {
                CP16(vst + (uint32_t)(r * 144 + c * 16),
                     (const char*)(Vh + (vrow + r) * NN_ + nb * 64 + c * 8));
            }
        }
    };

    // K resident (hi only, 18KB) + first Q/V stages
    for (int i = tid; i < 1024; i += 256) {
        int r = i >> 3, c = i & 7;
        CP16(sb + (uint32_t)(r * 144 + c * 16),
             (const char*)(Khi + (arow + r) * DD + coff + c * 8));
    }
    load_QV(0); CP_COMMIT();
    load_QV(1); CP_COMMIT();

    const int gid = lane >> 2, tig = lane & 3;
    const long long ebase = (long long)bh * NN_ * NN_;
    const int mrow = m0 + wid * 16 + gid;

    float rs0 = 0.0f, rs1 = 0.0f;
    float facc[8][4];
#pragma unroll
    for (int i = 0; i < 8; i++)
#pragma unroll
        for (int c = 0; c < 4; c++) facc[i][c] = 0.0f;

    for (int nb = 0; nb < 64; nb++) {
        if (nb < 63) CP_WAIT1(); else CP_WAIT0();
        __syncthreads();
        if (nb + 2 < 64) { load_QV(nb + 2); CP_COMMIT(); }

        const uint32_t Qst = sb + FU_Q0 + (uint32_t)(nb % 3) * FU_QST;
        const uint32_t Vst = sb + FU_V0 + (uint32_t)(nb % 3) * FU_VST;

        float sacc[8][4];
#pragma unroll
        for (int i = 0; i < 8; i++)
#pragma unroll
            for (int c = 0; c < 4; c++) sacc[i][c] = 0.0f;

        // scores: SINGLE fp16 product K_hi x Q_hi
#pragma unroll
        for (int kc = 0; kc < 4; kc++) {
            const uint32_t colA = (uint32_t)(kc * 32 + ((lane >> 4) & 1) * 16);
            const uint32_t colB = (uint32_t)(kc * 32 + ((lane >> 3) & 1) * 16);
            uint32_t a0, a1, a2, a3;
            ldsm4(a0, a1, a2, a3,
                  sb + (uint32_t)((wid * 16 + (lane & 15)) * 144) + colA);
#pragma unroll
            for (int j = 0; j < 4; j++) {
                int n = j * 16 + ((lane >> 4) & 1) * 8 + (lane & 7);
                uint32_t q0, q1, q2, q3;
                ldsm4(q0, q1, q2, q3, Qst + (uint32_t)(n * 144) + colB);
                mma16816h(sacc[2 * j],     a0, a1, a2, a3, q0, q1);
                mma16816h(sacc[2 * j + 1], a0, a1, a2, a3, q2, q3);
            }
        }

#pragma unroll
        for (int kch = 0; kch < 4; kch++) {
            uint32_t a0, a1, a2, a3;
#pragma unroll
            for (int jj = 0; jj < 2; jj++) {
                int j = 2 * kch + jj;
                float e0 = __expf(0.125f * sacc[j][0]);
                float e1 = __expf(0.125f * sacc[j][1]);
                float e2 = __expf(0.125f * sacc[j][2]);
                float e3 = __expf(0.125f * sacc[j][3]);
                rs0 += e0 + e1;
                rs1 += e2 + e3;
                __half2 h01 = __floats2half2_rn(e0, e1);
                __half2 h23 = __floats2half2_rn(e2, e3);
                long long colg = (long long)nb * 64 + j * 8 + tig * 2;
                *reinterpret_cast<uint32_t*>(E + ebase + (long long)mrow * NN_ + colg) =
                    *reinterpret_cast<uint32_t*>(&h01);
                *reinterpret_cast<uint32_t*>(E + ebase + (long long)(mrow + 8) * NN_ + colg) =
                    *reinterpret_cast<uint32_t*>(&h23);
                if (jj == 0) { a0 = *reinterpret_cast<uint32_t*>(&h01);
                               a1 = *reinterpret_cast<uint32_t*>(&h23); }
                else         { a2 = *reinterpret_cast<uint32_t*>(&h01);
                               a3 = *reinterpret_cast<uint32_t*>(&h23); }
            }
            const uint32_t colV = (uint32_t)(kch * 32 + ((lane >> 3) & 1) * 16);
#pragma unroll
            for (int vj = 0; vj < 4; vj++) {
                int n = vj * 16 + ((lane >> 4) & 1) * 8 + (lane & 7);
                uint32_t v0, v1, v2, v3;
                ldsm4(v0, v1, v2, v3, Vst + (uint32_t)(n * 144) + colV);
                mma16816h(facc[2 * vj],     a0, a1, a2, a3, v0, v1);
                mma16816h(facc[2 * vj + 1], a0, a1, a2, a3, v2, v3);
            }
        }
    }

    rs0 += __shfl_xor_sync(~0u, rs0, 1);
    rs0 += __shfl_xor_sync(~0u, rs0, 2);
    rs1 += __shfl_xor_sync(~0u, rs1, 1);
    rs1 += __shfl_xor_sync(~0u, rs1, 2);
    const float inv0 = __frcp_rn(rs0);
    const float inv1 = __frcp_rn(rs1);
    if (tig == 0) {
        rowsum[(long long)bh * NN_ + mrow]     = rs0;
        rowsum[(long long)bh * NN_ + mrow + 8] = rs1;
    }

#pragma unroll
    for (int n8 = 0; n8 < 8; n8++) {
        int col = h * DK + n8 * 8 + tig * 2;
#pragma unroll
        for (int half = 0; half < 2; half++) {
            long long row = (long long)(b * NN_ + mrow + half * 8);
            float inv = half ? inv1 : inv0;
            float v0 = facc[n8][half * 2 + 0] * inv;
            float v1 = facc[n8][half * 2 + 1] * inv;
            __half h0, l0, h1, l1;
            split1h(v0, h0, l0); split1h(v1, h1, l1);
            uint32_t ph = ((uint32_t)*(uint16_t*)&h1 << 16) | *(uint16_t*)&h0;
            uint32_t pl = ((uint32_t)*(uint16_t*)&l1 << 16) | *(uint16_t*)&l0;
            *reinterpret_cast<uint32_t*>(Fhi + row * DD + col) = ph;
            *reinterpret_cast<uint32_t*>(Flo + row * DD + col) = pl;
        }
    }
}

// ---------------------------------------------------------------------------
// attn_norm: attn[row, :] = float(E[row, :]) * rcp(rowsum[row])
// ---------------------------------------------------------------------------
__global__ void __launch_bounds__(256)
attn_norm(const __half* __restrict__ E, const float* __restrict__ rowsum,
          float* __restrict__ A)
{
    const long long row = blockIdx.x;
    const float inv = __frcp_rn(rowsum[row]);
    const uint2* pe = reinterpret_cast<const uint2*>(E + row * (long long)NN_);
    float4* pa = reinterpret_cast<float4*>(A + row * (long long)NN_);
    const int t = threadIdx.x;
#pragma unroll
    for (int i = 0; i < 4; i++) {
        uint2 u = pe[t + i * 256];
        __half2 a = *reinterpret_cast<__half2*>(&u.x);
        __half2 bq = *reinterpret_cast<__half2*>(&u.y);
        float2 fa = __half22float2(a);
        float2 fb = __half22float2(bq);
        float4 o;
        o.x = fa.x * inv; o.y = fa.y * inv;
        o.z = fb.x * inv; o.w = fb.y * inv;
        pa[t + i * 256] = o;
    }
}

// ---------------------------------------------------------------------------
// In-place row LayerNorm
// ---------------------------------------------------------------------------
__global__ void layernorm_rows(float* __restrict__ y,
                               const float* __restrict__ gamma,
                               const float* __restrict__ beta)
{
    const long long base = (long long)blockIdx.x * DD;
    const int t = threadIdx.x;
    const int lane = t & 31, warp = t >> 5;
    __shared__ float red[32];

    float x0 = y[base + t];
    float x1 = y[base + t + 256];

    float s = x0 + x1;
#pragma unroll
    for (int o = 16; o > 0; o >>= 1) s += __shfl_xor_sync(~0u, s, o);
    if (lane == 0) red[warp] = s;
    __syncthreads();
    if (warp == 0) {
        float x = (lane < 8) ? red[lane] : 0.0f;
#pragma unroll
        for (int o = 16; o > 0; o >>= 1) x += __shfl_xor_sync(~0u, x, o);
        if (lane == 0) red[0] = x;
    }
    __syncthreads();
    const float mu = red[0] * (1.0f / DD);
    __syncthreads();

    const float d0 = x0 - mu, d1 = x1 - mu;
    float v = d0 * d0 + d1 * d1;
#pragma unroll
    for (int o = 16; o > 0; o >>= 1) v += __shfl_xor_sync(~0u, v, o);
    if (lane == 0) red[warp] = v;
    __syncthreads();
    if (warp == 0) {
        float x = (lane < 8) ? red[lane] : 0.0f;
#pragma unroll
        for (int o = 16; o > 0; o >>= 1) x += __shfl_xor_sync(~0u, x, o);
        if (lane == 0) red[0] = x;
    }
    __syncthreads();
    const float r = rsqrtf(red[0] * (1.0f / DD) + 1e-5f);

    y[base + t]       = d0 * r * gamma[t]       + beta[t];
    y[base + t + 256] = d1 * r * gamma[t + 256] + beta[t + 256];
}

// ---------------------------------------------------------------------------
extern "C" void kernel_launch(void* const* d_in, const int* in_sizes, int n_in,
                              void* d_out, int out_size)
{
    const float* q    = (const float*)d_in[0];
    const float* k    = (const float*)d_in[1];
    const float* v    = (const float*)d_in[2];
    const float* w_q  = (const float*)d_in[3];
    const float* w_k  = (const float*)d_in[4];
    const float* w_v  = (const float*)d_in[5];
    const float* w_fc = (const float*)d_in[6];
    const float* gam  = (const float*)d_in[7];
    const float* bet  = (const float*)d_in[8];

    float* out  = (float*)d_out;                          // [B,N,D]
    float* attn = out + (long long)BB * NN_ * DD;         // [B,H,N,N]

    float* rsum;
    __half* eptr;
    cudaGetSymbolAddress((void**)&rsum, g_rowsum);
    cudaGetSymbolAddress((void**)&eptr, g_e);
    __half *xqh, *xql, *xkh, *xkl, *xvh, *xvl;
    __half *wqh, *wkh, *wvh, *wfh;
    __half *qph, *kph, *vth, *fth, *ftl;
    cudaGetSymbolAddress((void**)&xqh, g_xq_h); cudaGetSymbolAddress((void**)&xql, g_xq_l);
    cudaGetSymbolAddress((void**)&xkh, g_xk_h); cudaGetSymbolAddress((void**)&xkl, g_xk_l);
    cudaGetSymbolAddress((void**)&xvh, g_xv_h); cudaGetSymbolAddress((void**)&xvl, g_xv_l);
    cudaGetSymbolAddress((void**)&wqh, g_wq_h);
    cudaGetSymbolAddress((void**)&wkh, g_wk_h);
    cudaGetSymbolAddress((void**)&wvh, g_wv_h);
    cudaGetSymbolAddress((void**)&wfh, g_wf_h);
    cudaGetSymbolAddress((void**)&qph, g_qp_h);
    cudaGetSymbolAddress((void**)&kph, g_kp_h);
    cudaGetSymbolAddress((void**)&vth, g_vpt_h);
    cudaGetSymbolAddress((void**)&fth, g_ft_h); cudaGetSymbolAddress((void**)&ftl, g_ft_l);

    cudaFuncSetAttribute(proj_gemm,  cudaFuncAttributeMaxDynamicSharedMemorySize, GM_SMEM);
    cudaFuncSetAttribute(fc_gemm,    cudaFuncAttributeMaxDynamicSharedMemorySize, GM_SMEM);
    cudaFuncSetAttribute(fused_attn, cudaFuncAttributeMaxDynamicSharedMemorySize, FU_SMEM);

    const int M = BB * NN_;          // 8192
    const int n4i = M * DD / 4;
    const int n4w = DD * DD / 4;

    // 1) splits/conversions
    split3h<<<dim3((n4i + 255) / 256, 3), 256>>>(q, k, v, xqh, xkh, xvh, xql, xkl, xvl, n4i);
    conv4h<<<dim3((n4w + 255) / 256, 4), 256>>>(w_q, w_k, w_v, w_fc, wqh, wkh, wvh, wfh, n4w);

    // 2) projections (Q/K fp16-hi out; V transposed fp16 out)
    proj_gemm<<<dim3(DD / 128, M / 64, 3), 256, GM_SMEM>>>(
        xqh, xql, xkh, xkl, xvh, xvl,
        wqh, wkh, wvh,
        qph, kph, vth);

    // 3) fused attention (single-product fp16 scores)
    fused_attn<<<dim3(NN_ / 128, BB * HH), 256, FU_SMEM>>>(
        kph, qph, vth, eptr, rsum, fth, ftl);

    // 4) normalize attn into output region
    attn_norm<<<BB * HH * NN_, 256>>>(eptr, rsum, attn);

    // 5) fc + residual
    fc_gemm<<<dim3(DD / 128, M / 64), 256, GM_SMEM>>>(fth, ftl, wfh, out, q);

    // 6) LayerNorm
    layernorm_rows<<<M, 256>>>(out, gam, bet);
}